// round 1
// baseline (speedup 1.0000x reference)
#include <cuda_runtime.h>
#include <math.h>

#define BB 512
#define TT 24
#define VV 30
#define KP 752      // padded gate K (750 -> 752)
#define NPG 1280    // padded gate N (1250 -> 1280)
#define SWID 752    // state row width: x[0:250) m[250:750) pad[750:752)

// Head packed dims
#define HW1 (752*512)
#define HW2 (512*320)
#define HW3 (320*256)
#define HW4 (256*128)
#define HW5 (128*64)
#define WH_TOT (HW1+HW2+HW3+HW4+HW5)

// -------- device scratch (no allocation allowed) --------
__device__ __align__(16) float g_W[6][(size_t)KP*NPG];
__device__ __align__(16) float g_bias[6][NPG];
__device__ __align__(16) float g_E[VV][NPG];
__device__ __align__(16) float g_state[2][BB*SWID];
__device__ __align__(16) float g_h0[BB*512];
__device__ __align__(16) float g_h1[BB*512];
__device__ __align__(16) float g_logits[BB*64];
__device__ __align__(16) float g_WH[WH_TOT];
__device__ __align__(16) float g_bH[512+320+256+128+64];

// -------- f32x2 packed helpers --------
__device__ __forceinline__ unsigned long long dup_f32x2(float x){
    unsigned long long r;
    asm("mov.b64 %0, {%1, %1};" : "=l"(r) : "f"(x));
    return r;
}
__device__ __forceinline__ void fma_f32x2(unsigned long long& d, unsigned long long a, unsigned long long b){
    asm("fma.rn.f32x2 %0, %1, %2, %0;" : "+l"(d) : "l"(a), "l"(b));
}
__device__ __forceinline__ float2 unpack_f32x2(unsigned long long v){
    float2 f;
    asm("mov.b64 {%0, %1}, %2;" : "=f"(f.x), "=f"(f.y) : "l"(v));
    return f;
}

// -------- packing kernels (run every launch; deterministic) --------
__global__ void pack_gates(const float* __restrict__ w1_sv, const float* __restrict__ w1_mem,
                           const float* __restrict__ w1_sw,
                           const float* __restrict__ w_sv, const float* __restrict__ w_mem,
                           const float* __restrict__ w_sw)
{
    long long idx = (long long)blockIdx.x * blockDim.x + threadIdx.x;
    const long long total = 6LL * KP * NPG;
    if (idx >= total) return;
    int c = (int)(idx % NPG);
    long long t = idx / NPG;
    int k = (int)(t % KP);
    int l = (int)(t / KP);
    float v = 0.f;
    if (k < 750 && c < 1250){
        if (c < 1000){
            int j = c >> 1;
            if ((c & 1) == 0)
                v = (l==0) ? w1_sw[k*500+j] : w_sw[(size_t)(l-1)*750*500 + (size_t)k*500 + j];
            else
                v = (l==0) ? w1_mem[k*500+j] : w_mem[(size_t)(l-1)*750*500 + (size_t)k*500 + j];
        } else {
            int j = c - 1000;
            v = (l==0) ? w1_sv[k*250+j] : w_sv[(size_t)(l-1)*750*250 + (size_t)k*250 + j];
        }
    }
    g_W[l][(size_t)k*NPG + c] = v;
}

__global__ void pack_misc(const float* __restrict__ b1_sv, const float* __restrict__ b1_mem,
                          const float* __restrict__ b1_sw,
                          const float* __restrict__ b_sv, const float* __restrict__ b_mem,
                          const float* __restrict__ b_sw,
                          const float* __restrict__ w1_sv, const float* __restrict__ w1_mem,
                          const float* __restrict__ w1_sw,
                          const float* __restrict__ wp1, const float* __restrict__ bp1,
                          const float* __restrict__ wp2, const float* __restrict__ bp2,
                          const float* __restrict__ wp3, const float* __restrict__ bp3,
                          const float* __restrict__ wp4, const float* __restrict__ bp4,
                          const float* __restrict__ wp5, const float* __restrict__ bp5)
{
    long long idx = (long long)blockIdx.x * blockDim.x + threadIdx.x;
    const int S0 = 6*NPG;                 // gate biases
    const int S1 = S0 + VV*NPG;           // E rows (one-hot fold)
    const int S2 = S1 + 2*BB*SWID;        // state zero
    const int S3 = S2 + WH_TOT;           // head weights
    const int S4 = S3 + (512+320+256+128+64);
    if (idx >= S4) return;
    if (idx < S0){
        int l = (int)(idx / NPG), c = (int)(idx % NPG);
        float v = 0.f;
        if (c < 1000){
            int j = c >> 1;
            if (!(c & 1)) v = (l==0) ? b1_sw[j]  : b_sw[(l-1)*500+j];
            else          v = (l==0) ? b1_mem[j] : b_mem[(l-1)*500+j];
        } else if (c < 1250){
            v = (l==0) ? b1_sv[c-1000] : b_sv[(l-1)*250 + (c-1000)];
        }
        g_bias[l][c] = v;
    } else if (idx < S1){
        int q = (int)(idx - S0); int vv = q / NPG, c = q % NPG;
        int k = 750 + vv;
        float v = 0.f;
        if (c < 1000){
            int j = c >> 1;
            v = (c & 1) ? w1_mem[k*500+j] : w1_sw[k*500+j];
        } else if (c < 1250){
            v = w1_sv[k*250 + (c-1000)];
        }
        g_E[vv][c] = v;
    } else if (idx < S2){
        ((float*)g_state)[idx - S1] = 0.f;
    } else if (idx < S3){
        int q = (int)(idx - S2);
        const int off1 = HW1, off2 = HW1+HW2, off3 = HW1+HW2+HW3, off4 = HW1+HW2+HW3+HW4;
        int l, qi;
        if      (q < off1){ l=0; qi=q; }
        else if (q < off2){ l=1; qi=q-off1; }
        else if (q < off3){ l=2; qi=q-off2; }
        else if (q < off4){ l=3; qi=q-off3; }
        else              { l=4; qi=q-off4; }
        const int Npd[5] = {512,320,256,128,64};
        const int Ks[5]  = {750,450,300,200,100};
        const int Ns[5]  = {450,300,200,100,30};
        const float* wp[5] = {wp1,wp2,wp3,wp4,wp5};
        int k = qi / Npd[l], c = qi % Npd[l];
        g_WH[q] = (k < Ks[l] && c < Ns[l]) ? wp[l][k*Ns[l]+c] : 0.f;
    } else {
        int q = (int)(idx - S3);
        int l, c;
        if      (q < 512)  { l=0; c=q; }
        else if (q < 832)  { l=1; c=q-512; }
        else if (q < 1088) { l=2; c=q-832; }
        else if (q < 1216) { l=3; c=q-1088; }
        else               { l=4; c=q-1216; }
        const int Ns[5] = {450,300,200,100,30};
        const float* bp[5] = {bp1,bp2,bp3,bp4,bp5};
        g_bH[q] = (c < Ns[l]) ? bp[l][c] : 0.f;
    }
}

// -------- fused GEMM: 64x64 tile, 256 threads, 4x4 per-thread, f32x2 FMAs --------
// MODE 0: gate epilogue (sigmoid/tanh state update, interleaved sw/mem pairs)
// MODE 1: tanh epilogue (head layers)
// MODE 2: identity (logits)
template<int MODE>
__global__ __launch_bounds__(256) void gemm_fused(
    const float* __restrict__ A, int lda,          // [512 x K], also state_in for MODE 0
    const float* __restrict__ W, int nld,          // [K x nld], nld = padded N
    const float* __restrict__ bias,                // [nld]
    const float* __restrict__ E,                   // [30 x 1280] or nullptr
    const int* __restrict__ lettersT,              // letters + t (stride TT) or nullptr
    int K,
    float* __restrict__ out, int ldo)
{
    __shared__ __align__(16) float As[2][16][68];  // K-major, padded
    __shared__ __align__(16) float Bs[2][16][64];

    int tid = threadIdx.x;
    int tx = tid & 15, ty = tid >> 4;
    int m0 = blockIdx.y * 64, n0 = blockIdx.x * 64;

    unsigned long long acc[4][2];
    #pragma unroll
    for (int i = 0; i < 4; i++){ acc[i][0] = 0ULL; acc[i][1] = 0ULL; }

    int ar = tid >> 2;            // 0..63 (A row in tile)
    int ak = (tid & 3) * 4;       // 0,4,8,12 (A k offset)
    int br = tid >> 4;            // 0..15 (B k row)
    int bc = (tid & 15) * 4;      // 0..60 (B col)

    const float* Ap = A + (size_t)(m0 + ar) * lda + ak;
    const float* Wp = W + (size_t)br * nld + n0 + bc;

    {
        float4 a = *(const float4*)Ap;
        float4 b = *(const float4*)Wp;
        As[0][ak+0][ar] = a.x; As[0][ak+1][ar] = a.y;
        As[0][ak+2][ar] = a.z; As[0][ak+3][ar] = a.w;
        *(float4*)&Bs[0][br][bc] = b;
    }
    __syncthreads();

    int nk = K >> 4;
    for (int kt = 0; kt < nk; kt++){
        int cur = kt & 1;
        float4 an, bn;
        if (kt + 1 < nk){
            an = *(const float4*)(Ap + (kt+1)*16);
            bn = *(const float4*)(Wp + (size_t)(kt+1)*16*nld);
        }
        #pragma unroll
        for (int k = 0; k < 16; k++){
            ulonglong2 bp = *(const ulonglong2*)&Bs[cur][k][tx*4];
            float4 av = *(const float4*)&As[cur][k][ty*4];
            unsigned long long d0 = dup_f32x2(av.x);
            unsigned long long d1 = dup_f32x2(av.y);
            unsigned long long d2 = dup_f32x2(av.z);
            unsigned long long d3 = dup_f32x2(av.w);
            fma_f32x2(acc[0][0], d0, bp.x); fma_f32x2(acc[0][1], d0, bp.y);
            fma_f32x2(acc[1][0], d1, bp.x); fma_f32x2(acc[1][1], d1, bp.y);
            fma_f32x2(acc[2][0], d2, bp.x); fma_f32x2(acc[2][1], d2, bp.y);
            fma_f32x2(acc[3][0], d3, bp.x); fma_f32x2(acc[3][1], d3, bp.y);
        }
        if (kt + 1 < nk){
            __syncthreads();
            int nxt = cur ^ 1;
            As[nxt][ak+0][ar] = an.x; As[nxt][ak+1][ar] = an.y;
            As[nxt][ak+2][ar] = an.z; As[nxt][ak+3][ar] = an.w;
            *(float4*)&Bs[nxt][br][bc] = bn;
            __syncthreads();
        }
    }

    // ---- epilogue ----
    #pragma unroll
    for (int i = 0; i < 4; i++){
        int r = m0 + ty*4 + i;
        const float* erow = nullptr;
        if (E) erow = E + (size_t)lettersT[r*TT] * NPG;
        #pragma unroll
        for (int j2 = 0; j2 < 2; j2++){
            int c = n0 + tx*4 + j2*2;      // even; pair = (c, c+1)
            float2 z = unpack_f32x2(acc[i][j2]);
            z.x += bias[c]; z.y += bias[c+1];
            if (E){ z.x += erow[c]; z.y += erow[c+1]; }
            if (MODE == 0){
                if (c < 1000){
                    int j = c >> 1;                    // 0..499
                    float s  = 1.f / (1.f + expf(-z.x));     // sigmoid(z_sw)
                    float mo = A[(size_t)r*SWID + 250 + j];  // old m
                    out[(size_t)r*SWID + 250 + j] = mo*s + tanhf(z.y)*(1.f - s);
                } else if (c < 1250){
                    out[(size_t)r*SWID + (c-1000)] = tanhf(z.x);
                    if (c + 1 < 1250) out[(size_t)r*SWID + (c-999)] = tanhf(z.y);
                }
            } else if (MODE == 1){
                out[(size_t)r*ldo + c]   = tanhf(z.x);
                out[(size_t)r*ldo + c+1] = tanhf(z.y);
            } else {
                out[(size_t)r*ldo + c]   = z.x;
                out[(size_t)r*ldo + c+1] = z.y;
            }
        }
    }
}

// -------- softmax over 30 classes, one warp per row --------
__global__ void softmax_k(const float* __restrict__ logits, float* __restrict__ out){
    int gw = blockIdx.x * 8 + (threadIdx.x >> 5);
    int lane = threadIdx.x & 31;
    if (gw >= BB) return;
    float v = (lane < VV) ? logits[gw*64 + lane] : -3.0e38f;
    float mx = v;
    #pragma unroll
    for (int o = 16; o > 0; o >>= 1) mx = fmaxf(mx, __shfl_xor_sync(0xffffffffu, mx, o));
    float e = (lane < VV) ? expf(v - mx) : 0.f;
    float s = e;
    #pragma unroll
    for (int o = 16; o > 0; o >>= 1) s += __shfl_xor_sync(0xffffffffu, s, o);
    if (lane < VV) out[gw*VV + lane] = e / s;
}

extern "C" void kernel_launch(void* const* d_in, const int* in_sizes, int n_in,
                              void* d_out, int out_size)
{
    (void)in_sizes; (void)n_in; (void)out_size;
    const int*   letters = (const int*)  d_in[0];
    const float* w1_sv   = (const float*)d_in[1];
    const float* b1_sv   = (const float*)d_in[2];
    const float* w1_mem  = (const float*)d_in[3];
    const float* b1_mem  = (const float*)d_in[4];
    const float* w1_sw   = (const float*)d_in[5];
    const float* b1_sw   = (const float*)d_in[6];
    const float* w_sv    = (const float*)d_in[7];
    const float* b_sv    = (const float*)d_in[8];
    const float* w_mem   = (const float*)d_in[9];
    const float* b_mem   = (const float*)d_in[10];
    const float* w_sw    = (const float*)d_in[11];
    const float* b_sw    = (const float*)d_in[12];
    const float* wp1     = (const float*)d_in[13];
    const float* bp1     = (const float*)d_in[14];
    const float* wp2     = (const float*)d_in[15];
    const float* bp2     = (const float*)d_in[16];
    const float* wp3     = (const float*)d_in[17];
    const float* bp3     = (const float*)d_in[18];
    const float* wp4     = (const float*)d_in[19];
    const float* bp4     = (const float*)d_in[20];
    const float* wp5     = (const float*)d_in[21];
    const float* bp5     = (const float*)d_in[22];

    float *pW, *pBias, *pE, *pState, *pH0, *pH1, *pLog, *pWH, *pBH;
    cudaGetSymbolAddress((void**)&pW,     g_W);
    cudaGetSymbolAddress((void**)&pBias,  g_bias);
    cudaGetSymbolAddress((void**)&pE,     g_E);
    cudaGetSymbolAddress((void**)&pState, g_state);
    cudaGetSymbolAddress((void**)&pH0,    g_h0);
    cudaGetSymbolAddress((void**)&pH1,    g_h1);
    cudaGetSymbolAddress((void**)&pLog,   g_logits);
    cudaGetSymbolAddress((void**)&pWH,    g_WH);
    cudaGetSymbolAddress((void**)&pBH,    g_bH);

    // repack weights + zero state (every call; deterministic)
    {
        long long total = 6LL * KP * NPG;
        pack_gates<<<(unsigned)((total + 255) / 256), 256>>>(w1_sv, w1_mem, w1_sw, w_sv, w_mem, w_sw);
        const int S4 = 6*NPG + VV*NPG + 2*BB*SWID + WH_TOT + (512+320+256+128+64);
        pack_misc<<<(S4 + 255) / 256, 256>>>(b1_sv, b1_mem, b1_sw, b_sv, b_mem, b_sw,
                                             w1_sv, w1_mem, w1_sw,
                                             wp1, bp1, wp2, bp2, wp3, bp3, wp4, bp4, wp5, bp5);
    }

    // 24 steps x 6 gates, ping-pong state
    dim3 gGate(NPG/64, BB/64);
    for (int g = 0; g < TT*6; g++){
        int t = g / 6, l = g % 6;
        int cur = g & 1, nxt = cur ^ 1;
        const float* Ept = (l == 0) ? pE : nullptr;
        const int*   lt  = (l == 0) ? letters + t : nullptr;
        gemm_fused<0><<<gGate, 256>>>(pState + (size_t)cur*BB*SWID, SWID,
                                      pW + (size_t)l*KP*NPG, NPG,
                                      pBias + (size_t)l*NPG, Ept, lt, KP,
                                      pState + (size_t)nxt*BB*SWID, SWID);
    }

    // head: 750->450->300->200->100->30 (padded 512/320/256/128/64)
    gemm_fused<1><<<dim3(8,8), 256>>>(pState, SWID, pWH,                     512, pBH,      nullptr, nullptr, KP,  pH0, 512);
    gemm_fused<1><<<dim3(5,8), 256>>>(pH0,    512,  pWH + HW1,               320, pBH+512,  nullptr, nullptr, 512, pH1, 320);
    gemm_fused<1><<<dim3(4,8), 256>>>(pH1,    320,  pWH + HW1+HW2,           256, pBH+832,  nullptr, nullptr, 320, pH0, 256);
    gemm_fused<1><<<dim3(2,8), 256>>>(pH0,    256,  pWH + HW1+HW2+HW3,       128, pBH+1088, nullptr, nullptr, 256, pH1, 128);
    gemm_fused<2><<<dim3(1,8), 256>>>(pH1,    128,  pWH + HW1+HW2+HW3+HW4,    64, pBH+1216, nullptr, nullptr, 128, pLog, 64);

    softmax_k<<<BB/8, 256>>>(pLog, (float*)d_out);
}

// round 3
// speedup vs baseline: 1.5215x; 1.5215x over previous
#include <cuda_runtime.h>
#include <cuda_bf16.h>
#include <math.h>
#include <cstdint>

#define BB 512
#define TT 24
#define VV 30
#define SWID 752        // fp32 state row: x[0:250) m[250:750) pad
#define KPRIME 2304     // 3 segments x 768
#define SEG 768
#define NPG 1280        // padded gate output cols
#define KC 64           // K chunk
#define NKC 36          // 2304/64
#define STAGES 3
#define STG_A (128*128) // 128 rows x 128B (64 bf16 cols)
#define STG_B (64*128)  // 64 rows x 128B
#define STG_BYTES (STG_A + STG_B)   // 24576
#define DSM_BYTES (STAGES * STG_BYTES)

// Head packed dims (fp32 CUDA-core path)
#define HW1 (752*512)
#define HW2 (512*320)
#define HW3 (320*256)
#define HW4 (256*128)
#define HW5 (128*64)
#define WH_TOT (HW1+HW2+HW3+HW4+HW5)

// -------- device scratch --------
__device__ __align__(16) __nv_bfloat16 g_Wt[6ULL*NPG*KPRIME];   // [l][n][k'] bf16, k-contiguous
__device__ __align__(16) __nv_bfloat16 g_Abf[2][BB*KPRIME];     // ping-pong activations
__device__ __align__(16) float g_bias[6][NPG];
__device__ __align__(16) float g_E[VV][NPG];
__device__ __align__(16) float g_state[2][BB*SWID];
__device__ __align__(16) float g_h0[BB*512];
__device__ __align__(16) float g_h1[BB*512];
__device__ __align__(16) float g_logits[BB*64];
__device__ __align__(16) float g_WH[WH_TOT];
__device__ __align__(16) float g_bH[512+320+256+128+64];

// ======================= helpers =======================
__device__ __forceinline__ uint32_t smem_u32(const void* p) {
    uint32_t a;
    asm("{ .reg .u64 t; cvta.to.shared.u64 t, %1; cvt.u32.u64 %0, t; }" : "=r"(a) : "l"(p));
    return a;
}
__device__ __forceinline__ void cp16(uint32_t dst, const void* src){
    asm volatile("cp.async.cg.shared.global [%0], [%1], 16;" :: "r"(dst), "l"(src) : "memory");
}
#define CP_COMMIT() asm volatile("cp.async.commit_group;" ::: "memory")
#define CP_WAIT2()  asm volatile("cp.async.wait_group 2;" ::: "memory")
#define CP_WAIT0()  asm volatile("cp.async.wait_group 0;" ::: "memory")

__device__ __forceinline__ uint32_t lds32(uint32_t addr){
    uint32_t v;
    asm volatile("ld.shared.b32 %0, [%1];" : "=r"(v) : "r"(addr));
    return v;
}
__device__ __forceinline__ void mma_bf16(float* d, uint32_t a0, uint32_t a1, uint32_t a2, uint32_t a3,
                                         uint32_t b0, uint32_t b1){
    asm volatile("mma.sync.aligned.m16n8k16.row.col.f32.bf16.bf16.f32 "
                 "{%0,%1,%2,%3}, {%4,%5,%6,%7}, {%8,%9}, {%0,%1,%2,%3};"
                 : "+f"(d[0]), "+f"(d[1]), "+f"(d[2]), "+f"(d[3])
                 : "r"(a0), "r"(a1), "r"(a2), "r"(a3), "r"(b0), "r"(b1));
}

// ======================= packing kernels =======================
__global__ void pack_wt(const float* __restrict__ w1_sv, const float* __restrict__ w1_mem,
                        const float* __restrict__ w1_sw,
                        const float* __restrict__ w_sv, const float* __restrict__ w_mem,
                        const float* __restrict__ w_sw)
{
    long long idx = (long long)blockIdx.x * blockDim.x + threadIdx.x;
    const long long total = 6LL * NPG * KPRIME;
    if (idx >= total) return;
    int kp = (int)(idx % KPRIME);
    long long t2 = idx / KPRIME;
    int n = (int)(t2 % NPG);
    int l = (int)(t2 / NPG);
    int seg = kp / SEG, k = kp % SEG;
    float w = 0.f;
    if (k < 750 && n < 1250){
        if (n < 1000){
            int j = n >> 1;
            if (!(n & 1)) w = (l==0) ? w1_sw[k*500+j]  : w_sw[(size_t)(l-1)*375000 + (size_t)k*500 + j];
            else          w = (l==0) ? w1_mem[k*500+j] : w_mem[(size_t)(l-1)*375000 + (size_t)k*500 + j];
        } else {
            int j = n - 1000;
            w = (l==0) ? w1_sv[k*250+j] : w_sv[(size_t)(l-1)*187500 + (size_t)k*250 + j];
        }
    }
    __nv_bfloat16 v;
    if (seg == 1){
        __nv_bfloat16 h = __float2bfloat16(w);
        v = __float2bfloat16(w - __bfloat162float(h));
    } else {
        v = __float2bfloat16(w);
    }
    g_Wt[idx] = v;
}

__global__ void pack_misc(const float* __restrict__ b1_sv, const float* __restrict__ b1_mem,
                          const float* __restrict__ b1_sw,
                          const float* __restrict__ b_sv, const float* __restrict__ b_mem,
                          const float* __restrict__ b_sw,
                          const float* __restrict__ w1_sv, const float* __restrict__ w1_mem,
                          const float* __restrict__ w1_sw,
                          const float* __restrict__ wp1, const float* __restrict__ bp1,
                          const float* __restrict__ wp2, const float* __restrict__ bp2,
                          const float* __restrict__ wp3, const float* __restrict__ bp3,
                          const float* __restrict__ wp4, const float* __restrict__ bp4,
                          const float* __restrict__ wp5, const float* __restrict__ bp5)
{
    long long idx = (long long)blockIdx.x * blockDim.x + threadIdx.x;
    const int S0 = 6*NPG;
    const int S1 = S0 + VV*NPG;
    const int S2 = S1 + 2*BB*SWID;
    const int S3 = S2 + WH_TOT;
    const int S4 = S3 + (512+320+256+128+64);
    const long long S5 = (long long)S4 + 2LL*BB*KPRIME/2;   // zero g_Abf as u32
    if (idx >= S5) return;
    if (idx < S0){
        int l = (int)(idx / NPG), c = (int)(idx % NPG);
        float v = 0.f;
        if (c < 1000){
            int j = c >> 1;
            if (!(c & 1)) v = (l==0) ? b1_sw[j]  : b_sw[(l-1)*500+j];
            else          v = (l==0) ? b1_mem[j] : b_mem[(l-1)*500+j];
        } else if (c < 1250){
            v = (l==0) ? b1_sv[c-1000] : b_sv[(l-1)*250 + (c-1000)];
        }
        g_bias[l][c] = v;
    } else if (idx < S1){
        int q = (int)(idx - S0); int vv = q / NPG, c = q % NPG;
        int k = 750 + vv;
        float v = 0.f;
        if (c < 1000){
            int j = c >> 1;
            v = (c & 1) ? w1_mem[k*500+j] : w1_sw[k*500+j];
        } else if (c < 1250){
            v = w1_sv[k*250 + (c-1000)];
        }
        g_E[vv][c] = v;
    } else if (idx < S2){
        ((float*)g_state)[idx - S1] = 0.f;
    } else if (idx < S3){
        int q = (int)(idx - S2);
        const int off1 = HW1, off2 = HW1+HW2, off3 = HW1+HW2+HW3, off4 = HW1+HW2+HW3+HW4;
        int l, qi;
        if      (q < off1){ l=0; qi=q; }
        else if (q < off2){ l=1; qi=q-off1; }
        else if (q < off3){ l=2; qi=q-off2; }
        else if (q < off4){ l=3; qi=q-off3; }
        else              { l=4; qi=q-off4; }
        const int Npd[5] = {512,320,256,128,64};
        const int Ks[5]  = {750,450,300,200,100};
        const int Ns[5]  = {450,300,200,100,30};
        const float* wp[5] = {wp1,wp2,wp3,wp4,wp5};
        int k = qi / Npd[l], c = qi % Npd[l];
        g_WH[q] = (k < Ks[l] && c < Ns[l]) ? wp[l][k*Ns[l]+c] : 0.f;
    } else if (idx < S4){
        int q = (int)(idx - S3);
        int l, c;
        if      (q < 512)  { l=0; c=q; }
        else if (q < 832)  { l=1; c=q-512; }
        else if (q < 1088) { l=2; c=q-832; }
        else if (q < 1216) { l=3; c=q-1088; }
        else               { l=4; c=q-1216; }
        const int Ns[5] = {450,300,200,100,30};
        const float* bp[5] = {bp1,bp2,bp3,bp4,bp5};
        g_bH[q] = (c < Ns[l]) ? bp[l][c] : 0.f;
    } else {
        ((uint32_t*)g_Abf)[idx - S4] = 0u;
    }
}

// ======================= gate GEMM (HMMA bf16x3) =======================
// CTA 128x64, 8 warps as 4(m) x 2(n), warp tile 32x32.
// Smem rows are 128B (64 bf16), XOR-swizzled at 16B granularity: byte = row*128 + (bcol ^ ((row&7)<<4)).

__device__ __forceinline__ void load_chunk(uint32_t sbase,
                                           const __nv_bfloat16* __restrict__ Ain,
                                           const __nv_bfloat16* __restrict__ Wt,
                                           int m0, int n0, int ci, int tid)
{
    int kb = ci * KC;
    // A: 128 rows x 8 x16B  => 1024 cp16, 4 per thread
    #pragma unroll
    for (int p = 0; p < 4; p++){
        int q = p*256 + tid;         // 0..1023
        int j = q & 7, r = q >> 3;   // j: 16B block, r: row
        const __nv_bfloat16* src = Ain + (size_t)(m0 + r)*KPRIME + kb + j*8;
        uint32_t dst = sbase + (uint32_t)(r*128 + ((j*16) ^ ((r & 7) << 4)));
        cp16(dst, src);
    }
    // B: 64 rows x 8 x16B => 512 cp16, 2 per thread
    #pragma unroll
    for (int p = 0; p < 2; p++){
        int q = p*256 + tid;         // 0..511
        int j = q & 7, n = q >> 3;
        const __nv_bfloat16* src = Wt + (size_t)(n0 + n)*KPRIME + kb + j*8;
        uint32_t dst = sbase + STG_A + (uint32_t)(n*128 + ((j*16) ^ ((n & 7) << 4)));
        cp16(dst, src);
    }
}

__device__ __forceinline__ void writeA(__nv_bfloat16* __restrict__ Aout, int row, int k, float v){
    __nv_bfloat16 h = __float2bfloat16(v);
    float lo = v - __bfloat162float(h);
    __nv_bfloat16 lb = __float2bfloat16(lo);
    size_t base = (size_t)row*KPRIME + k;
    Aout[base]         = h;
    Aout[base + SEG]   = h;
    Aout[base + 2*SEG] = lb;
}

__global__ __launch_bounds__(256, 1) void gate_mma(
    const __nv_bfloat16* __restrict__ Ain,
    const __nv_bfloat16* __restrict__ Wt,
    const float* __restrict__ bias,
    const float* __restrict__ E,            // null unless layer 0
    const int* __restrict__ lettersT,       // letters + t, stride TT
    const float* __restrict__ stateIn,
    float* __restrict__ stateOut,
    __nv_bfloat16* __restrict__ Aout)
{
    extern __shared__ char dsm[];
    uint32_t sb = smem_u32(dsm);

    int tid = threadIdx.x;
    int wid = tid >> 5, lane = tid & 31;
    int wm = wid >> 1, wn = wid & 1;          // 4(m) x 2(n)
    int g = lane >> 2, tg = lane & 3;         // mma fragment coords
    int n0 = blockIdx.x * 64, m0 = blockIdx.y * 128;

    float acc[2][4][4];
    #pragma unroll
    for (int mi = 0; mi < 2; mi++)
        #pragma unroll
        for (int ni = 0; ni < 4; ni++)
            #pragma unroll
            for (int e = 0; e < 4; e++) acc[mi][ni][e] = 0.f;

    // per-lane invariant smem row bases (byte offsets within a stage)
    // A rows for this warp: wm*32 + mi*16 + g (+8)
    uint32_t aRow0 = (uint32_t)(wm*32 + g) * 128;       // mi=0, low half
    // B rows: wn*32 + ni*8 + g
    uint32_t bRow0 = (uint32_t)(wn*32 + g) * 128;
    uint32_t swz = (uint32_t)(g & 7) << 4;              // XOR term (row&7 == g for all our rows)
    uint32_t colA = (uint32_t)tg * 4;                   // a0 byte col base

    // prologue: prefetch chunks 0,1
    load_chunk(sb + 0*STG_BYTES, Ain, Wt, m0, n0, 0, tid); CP_COMMIT();
    load_chunk(sb + 1*STG_BYTES, Ain, Wt, m0, n0, 1, tid); CP_COMMIT();

    for (int i = 0; i < NKC; i++){
        if (i + 2 < NKC) load_chunk(sb + (uint32_t)((i+2)%STAGES)*STG_BYTES, Ain, Wt, m0, n0, i+2, tid);
        CP_COMMIT();
        CP_WAIT2();
        __syncthreads();          // chunk i visible to all

        uint32_t aB = sb + (uint32_t)(i%STAGES)*STG_BYTES;
        uint32_t bB = aB + STG_A;

        #pragma unroll
        for (int ks = 0; ks < 4; ks++){
            uint32_t kcol = (uint32_t)ks * 32;          // byte col of k16 block
            uint32_t c0 = (kcol + colA) ^ swz;          // a0/a1/b0
            uint32_t c1 = (kcol + colA + 16) ^ swz;     // a2/a3/b1
            // B fragments: 4 n8-tiles
            uint32_t b0[4], b1[4];
            #pragma unroll
            for (int ni = 0; ni < 4; ni++){
                uint32_t br = bB + bRow0 + (uint32_t)ni*8*128;
                b0[ni] = lds32(br + c0);
                b1[ni] = lds32(br + c1);
            }
            #pragma unroll
            for (int mi = 0; mi < 2; mi++){
                uint32_t ar = aB + aRow0 + (uint32_t)mi*16*128;
                uint32_t a0 = lds32(ar + c0);
                uint32_t a1 = lds32(ar + 8*128 + c0);
                uint32_t a2 = lds32(ar + c1);
                uint32_t a3 = lds32(ar + 8*128 + c1);
                #pragma unroll
                for (int ni = 0; ni < 4; ni++)
                    mma_bf16(acc[mi][ni], a0, a1, a2, a3, b0[ni], b1[ni]);
            }
        }
        __syncthreads();          // done reading stage before it is overwritten
    }

    // ---- epilogue (thread-local: each (c0,c1)/(c2,c3) is one even/odd col pair) ----
    #pragma unroll
    for (int mi = 0; mi < 2; mi++){
        #pragma unroll
        for (int h = 0; h < 2; h++){
            int row = m0 + wm*32 + mi*16 + g + h*8;
            int letter = E ? lettersT[row * TT] : 0;
            const float* er = E ? (E + (size_t)letter * NPG) : nullptr;
            #pragma unroll
            for (int ni = 0; ni < 4; ni++){
                int c = n0 + wn*32 + ni*8 + tg*2;   // even
                float z0 = acc[mi][ni][h*2+0] + bias[c];
                float z1 = acc[mi][ni][h*2+1] + bias[c+1];
                if (er){ z0 += er[c]; z1 += er[c+1]; }
                if (c < 1000){
                    int j = c >> 1;
                    float s  = 1.f / (1.f + expf(-z0));
                    float mo = stateIn[(size_t)row*SWID + 250 + j];
                    float mn = mo * s + tanhf(z1) * (1.f - s);
                    stateOut[(size_t)row*SWID + 250 + j] = mn;
                    writeA(Aout, row, 250 + j, mn);
                } else if (c < 1250){
                    float x0 = tanhf(z0);
                    stateOut[(size_t)row*SWID + (c-1000)] = x0;
                    writeA(Aout, row, c-1000, x0);
                    if (c + 1 < 1250){
                        float x1 = tanhf(z1);
                        stateOut[(size_t)row*SWID + (c-999)] = x1;
                        writeA(Aout, row, c-999, x1);
                    }
                }
            }
        }
    }
}

// ======================= head GEMM (fp32 f32x2 CUDA cores) =======================
__device__ __forceinline__ unsigned long long dup_f32x2(float x){
    unsigned long long r;
    asm("mov.b64 %0, {%1, %1};" : "=l"(r) : "f"(x));
    return r;
}
__device__ __forceinline__ void fma_f32x2(unsigned long long& d, unsigned long long a, unsigned long long b){
    asm("fma.rn.f32x2 %0, %1, %2, %0;" : "+l"(d) : "l"(a), "l"(b));
}
__device__ __forceinline__ float2 unpack_f32x2(unsigned long long v){
    float2 f;
    asm("mov.b64 {%0, %1}, %2;" : "=f"(f.x), "=f"(f.y) : "l"(v));
    return f;
}

template<int MODE>   // 1: tanh, 2: identity
__global__ __launch_bounds__(256) void gemm_fused(
    const float* __restrict__ A, int lda,
    const float* __restrict__ W, int nld,
    const float* __restrict__ bias,
    int K,
    float* __restrict__ out, int ldo)
{
    __shared__ __align__(16) float As[2][16][68];
    __shared__ __align__(16) float Bs[2][16][64];

    int tid = threadIdx.x;
    int tx = tid & 15, ty = tid >> 4;
    int m0 = blockIdx.y * 64, n0 = blockIdx.x * 64;

    unsigned long long acc[4][2];
    #pragma unroll
    for (int i = 0; i < 4; i++){ acc[i][0] = 0ULL; acc[i][1] = 0ULL; }

    int ar = tid >> 2;
    int ak = (tid & 3) * 4;
    int br = tid >> 4;
    int bc = (tid & 15) * 4;

    const float* Ap = A + (size_t)(m0 + ar) * lda + ak;
    const float* Wp = W + (size_t)br * nld + n0 + bc;

    {
        float4 a = *(const float4*)Ap;
        float4 b = *(const float4*)Wp;
        As[0][ak+0][ar] = a.x; As[0][ak+1][ar] = a.y;
        As[0][ak+2][ar] = a.z; As[0][ak+3][ar] = a.w;
        *(float4*)&Bs[0][br][bc] = b;
    }
    __syncthreads();

    int nk = K >> 4;
    for (int kt = 0; kt < nk; kt++){
        int cur = kt & 1;
        float4 an, bn;
        if (kt + 1 < nk){
            an = *(const float4*)(Ap + (kt+1)*16);
            bn = *(const float4*)(Wp + (size_t)(kt+1)*16*nld);
        }
        #pragma unroll
        for (int k = 0; k < 16; k++){
            ulonglong2 bp = *(const ulonglong2*)&Bs[cur][k][tx*4];
            float4 av = *(const float4*)&As[cur][k][ty*4];
            unsigned long long d0 = dup_f32x2(av.x);
            unsigned long long d1 = dup_f32x2(av.y);
            unsigned long long d2 = dup_f32x2(av.z);
            unsigned long long d3 = dup_f32x2(av.w);
            fma_f32x2(acc[0][0], d0, bp.x); fma_f32x2(acc[0][1], d0, bp.y);
            fma_f32x2(acc[1][0], d1, bp.x); fma_f32x2(acc[1][1], d1, bp.y);
            fma_f32x2(acc[2][0], d2, bp.x); fma_f32x2(acc[2][1], d2, bp.y);
            fma_f32x2(acc[3][0], d3, bp.x); fma_f32x2(acc[3][1], d3, bp.y);
        }
        if (kt + 1 < nk){
            __syncthreads();
            int nxt = cur ^ 1;
            As[nxt][ak+0][ar] = an.x; As[nxt][ak+1][ar] = an.y;
            As[nxt][ak+2][ar] = an.z; As[nxt][ak+3][ar] = an.w;
            *(float4*)&Bs[nxt][br][bc] = bn;
            __syncthreads();
        }
    }

    #pragma unroll
    for (int i = 0; i < 4; i++){
        int r = m0 + ty*4 + i;
        #pragma unroll
        for (int j2 = 0; j2 < 2; j2++){
            int c = n0 + tx*4 + j2*2;
            float2 z = unpack_f32x2(acc[i][j2]);
            z.x += bias[c]; z.y += bias[c+1];
            if (MODE == 1){
                out[(size_t)r*ldo + c]   = tanhf(z.x);
                out[(size_t)r*ldo + c+1] = tanhf(z.y);
            } else {
                out[(size_t)r*ldo + c]   = z.x;
                out[(size_t)r*ldo + c+1] = z.y;
            }
        }
    }
}

// -------- softmax over 30 classes --------
__global__ void softmax_k(const float* __restrict__ logits, float* __restrict__ out){
    int gw = blockIdx.x * 8 + (threadIdx.x >> 5);
    int lane = threadIdx.x & 31;
    if (gw >= BB) return;
    float v = (lane < VV) ? logits[gw*64 + lane] : -3.0e38f;
    float mx = v;
    #pragma unroll
    for (int o = 16; o > 0; o >>= 1) mx = fmaxf(mx, __shfl_xor_sync(0xffffffffu, mx, o));
    float e = (lane < VV) ? expf(v - mx) : 0.f;
    float s = e;
    #pragma unroll
    for (int o = 16; o > 0; o >>= 1) s += __shfl_xor_sync(0xffffffffu, s, o);
    if (lane < VV) out[gw*VV + lane] = e / s;
}

extern "C" void kernel_launch(void* const* d_in, const int* in_sizes, int n_in,
                              void* d_out, int out_size)
{
    (void)in_sizes; (void)n_in; (void)out_size;
    const int*   letters = (const int*)  d_in[0];
    const float* w1_sv   = (const float*)d_in[1];
    const float* b1_sv   = (const float*)d_in[2];
    const float* w1_mem  = (const float*)d_in[3];
    const float* b1_mem  = (const float*)d_in[4];
    const float* w1_sw   = (const float*)d_in[5];
    const float* b1_sw   = (const float*)d_in[6];
    const float* w_sv    = (const float*)d_in[7];
    const float* b_sv    = (const float*)d_in[8];
    const float* w_mem   = (const float*)d_in[9];
    const float* b_mem   = (const float*)d_in[10];
    const float* w_sw    = (const float*)d_in[11];
    const float* b_sw    = (const float*)d_in[12];
    const float* wp1     = (const float*)d_in[13];
    const float* bp1     = (const float*)d_in[14];
    const float* wp2     = (const float*)d_in[15];
    const float* bp2     = (const float*)d_in[16];
    const float* wp3     = (const float*)d_in[17];
    const float* bp3     = (const float*)d_in[18];
    const float* wp4     = (const float*)d_in[19];
    const float* bp4     = (const float*)d_in[20];
    const float* wp5     = (const float*)d_in[21];
    const float* bp5     = (const float*)d_in[22];

    static int smem_cfg = 0;
    if (!smem_cfg){
        cudaFuncSetAttribute(gate_mma, cudaFuncAttributeMaxDynamicSharedMemorySize, DSM_BYTES);
        smem_cfg = 1;
    }

    __nv_bfloat16 *pWt, *pAbf;
    float *pBias, *pE, *pState, *pH0, *pH1, *pLog, *pWH, *pBH;
    cudaGetSymbolAddress((void**)&pWt,    g_Wt);
    cudaGetSymbolAddress((void**)&pAbf,   g_Abf);
    cudaGetSymbolAddress((void**)&pBias,  g_bias);
    cudaGetSymbolAddress((void**)&pE,     g_E);
    cudaGetSymbolAddress((void**)&pState, g_state);
    cudaGetSymbolAddress((void**)&pH0,    g_h0);
    cudaGetSymbolAddress((void**)&pH1,    g_h1);
    cudaGetSymbolAddress((void**)&pLog,   g_logits);
    cudaGetSymbolAddress((void**)&pWH,    g_WH);
    cudaGetSymbolAddress((void**)&pBH,    g_bH);

    // pack weights (bf16 hi/lo 3-segment) + misc + zero state/activations
    {
        long long total = 6LL * NPG * KPRIME;
        pack_wt<<<(unsigned)((total + 255) / 256), 256>>>(w1_sv, w1_mem, w1_sw, w_sv, w_mem, w_sw);
        long long S5 = 6*NPG + VV*NPG + 2*BB*SWID + WH_TOT + (512+320+256+128+64) + 2LL*BB*KPRIME/2;
        pack_misc<<<(unsigned)((S5 + 255) / 256), 256>>>(b1_sv, b1_mem, b1_sw, b_sv, b_mem, b_sw,
                                                         w1_sv, w1_mem, w1_sw,
                                                         wp1, bp1, wp2, bp2, wp3, bp3, wp4, bp4, wp5, bp5);
    }

    // 24 steps x 6 gates (HMMA), ping-pong state + bf16 activations
    dim3 gGate(NPG/64, BB/128);   // 20 x 4 = 80 CTAs
    for (int g = 0; g < TT*6; g++){
        int t = g / 6, l = g % 6;
        int cur = g & 1, nxt = cur ^ 1;
        const float* Ept = (l == 0) ? pE : nullptr;
        const int*   lt  = (l == 0) ? letters + t : letters;
        gate_mma<<<gGate, 256, DSM_BYTES>>>(
            pAbf + (size_t)cur*BB*KPRIME,
            pWt  + (size_t)l*NPG*KPRIME,
            pBias + (size_t)l*NPG,
            Ept, lt,
            pState + (size_t)cur*BB*SWID,
            pState + (size_t)nxt*BB*SWID,
            pAbf + (size_t)nxt*BB*KPRIME);
    }

    // head: 750->450->300->200->100->30 (padded), fp32 CUDA-core GEMMs
    gemm_fused<1><<<dim3(8,8), 256>>>(pState, SWID, pWH,                   512, pBH,      752, pH0, 512);
    gemm_fused<1><<<dim3(5,8), 256>>>(pH0,    512,  pWH + HW1,             320, pBH+512,  512, pH1, 320);
    gemm_fused<1><<<dim3(4,8), 256>>>(pH1,    320,  pWH + HW1+HW2,         256, pBH+832,  320, pH0, 256);
    gemm_fused<1><<<dim3(2,8), 256>>>(pH0,    256,  pWH + HW1+HW2+HW3,     128, pBH+1088, 256, pH1, 128);
    gemm_fused<2><<<dim3(1,8), 256>>>(pH1,    128,  pWH + HW1+HW2+HW3+HW4,  64, pBH+1216, 128, pLog, 64);

    softmax_k<<<BB/8, 256>>>(pLog, (float*)d_out);
}